// round 16
// baseline (speedup 1.0000x reference)
#include <cuda_runtime.h>
#include <cuda_fp16.h>

#define NB 1024   // B
#define NL 50     // L
#define NLP 56    // L padded
#define NS 256    // S
#define NH 4      // H
#define NE 64     // E
#define NSUPP 10000
#define HSTRIDE 68
#define KH 72     // halves per K row in smem (144B, 16B-aligned, conflict-free)

// Scratch (device globals; no allocation allowed)
__device__ __half g_KsuppH[NH * NSUPP * NE];  // 5.12 MB (fp16)
__device__ float g_fea[2 * NB * NE];
__device__ float g_g[2 * NH * NB * NE];

__device__ __forceinline__ float fast_tanh(float x) {
    float e;
    asm("ex2.approx.f32 %0, %1;" : "=f"(e) : "f"(x * 2.8853900817779268f));
    float r;
    asm("rcp.approx.f32 %0, %1;" : "=f"(r) : "f"(e + 1.0f));
    return fmaf(-2.0f, r, 1.0f);
}
__device__ __forceinline__ float fast_rcp(float x) {
    float r;
    asm("rcp.approx.f32 %0, %1;" : "=f"(r) : "f"(x));
    return r;
}
__device__ __forceinline__ __half2 u2h2(unsigned u) {
    return *reinterpret_cast<__half2*>(&u);
}

__device__ __forceinline__ unsigned smem_u32(const void* p) {
    return (unsigned)__cvta_generic_to_shared(p);
}
__device__ __forceinline__ void mbar_init(unsigned mbar, unsigned count) {
    asm volatile("mbarrier.init.shared.b64 [%0], %1;" :: "r"(mbar), "r"(count) : "memory");
}
__device__ __forceinline__ void mbar_expect_tx(unsigned mbar, unsigned bytes) {
    asm volatile("mbarrier.arrive.expect_tx.shared.b64 _, [%0], %1;"
                 :: "r"(mbar), "r"(bytes) : "memory");
}
__device__ __forceinline__ void mbar_wait(unsigned mbar, unsigned parity) {
    asm volatile(
        "{\n\t"
        ".reg .pred P1;\n\t"
        "WAIT_LOOP_%=:\n\t"
        "mbarrier.try_wait.parity.shared.b64 P1, [%0], %1, 0x989680;\n\t"
        "@P1 bra.uni WAIT_DONE_%=;\n\t"
        "bra.uni WAIT_LOOP_%=;\n\t"
        "WAIT_DONE_%=:\n\t"
        "}"
        :: "r"(mbar), "r"(parity) : "memory");
}
__device__ __forceinline__ void bulk_copy128(void* smem_dst, const void* gmem_src,
                                             unsigned mbar) {
    asm volatile(
        "cp.async.bulk.shared::cta.global.mbarrier::complete_tx::bytes [%0], [%1], 128, [%2];"
        :: "r"(smem_u32(smem_dst)), "l"(gmem_src), "r"(mbar) : "memory");
}

// ---------------------------------------------------------------------------
// K0: K_supp[h][j][:] = half(tgt_user_emb[supp_users[j]] @ Wk[h])
// Triggers programmatic launch of encode after its stores.
// ---------------------------------------------------------------------------
__global__ void __launch_bounds__(256)
ksupp_kernel(const int* __restrict__ supp_users,
             const float* __restrict__ tgt_user_emb,
             const float* __restrict__ Wk) {
    extern __shared__ float Wks[];          // 64KB
    __shared__ float emb[16][NE];

    int tid = threadIdx.x;
    int j0 = blockIdx.x * 16;

    for (int i = tid; i < 4096; i += 256)
        reinterpret_cast<float4*>(Wks)[i] = reinterpret_cast<const float4*>(Wk)[i];
    for (int i = tid; i < 16 * NE; i += 256) {
        int j = i >> 6, e = i & 63;
        emb[j][e] = tgt_user_emb[supp_users[j0 + j] * NE + e];
    }
    __syncthreads();

    int h  = tid >> 6;
    int r  = tid & 63;
    int eb = (r & 15) * 4;
    int jb = (r >> 4) * 4;

    float acc[4][4];
#pragma unroll
    for (int a = 0; a < 4; a++)
#pragma unroll
        for (int c = 0; c < 4; c++) acc[a][c] = 0.f;

    const float* wbase = Wks + h * NE * NE + eb;
#pragma unroll 8
    for (int ep = 0; ep < NE; ep++) {
        float4 w = *reinterpret_cast<const float4*>(wbase + ep * NE);
        float e0 = emb[jb + 0][ep];
        float e1 = emb[jb + 1][ep];
        float e2 = emb[jb + 2][ep];
        float e3 = emb[jb + 3][ep];
        acc[0][0] = fmaf(e0, w.x, acc[0][0]); acc[0][1] = fmaf(e0, w.y, acc[0][1]);
        acc[0][2] = fmaf(e0, w.z, acc[0][2]); acc[0][3] = fmaf(e0, w.w, acc[0][3]);
        acc[1][0] = fmaf(e1, w.x, acc[1][0]); acc[1][1] = fmaf(e1, w.y, acc[1][1]);
        acc[1][2] = fmaf(e1, w.z, acc[1][2]); acc[1][3] = fmaf(e1, w.w, acc[1][3]);
        acc[2][0] = fmaf(e2, w.x, acc[2][0]); acc[2][1] = fmaf(e2, w.y, acc[2][1]);
        acc[2][2] = fmaf(e2, w.z, acc[2][2]); acc[2][3] = fmaf(e2, w.w, acc[2][3]);
        acc[3][0] = fmaf(e3, w.x, acc[3][0]); acc[3][1] = fmaf(e3, w.y, acc[3][1]);
        acc[3][2] = fmaf(e3, w.z, acc[3][2]); acc[3][3] = fmaf(e3, w.w, acc[3][3]);
    }
#pragma unroll
    for (int jj = 0; jj < 4; jj++) {
        __half2 h0 = __floats2half2_rn(acc[jj][0], acc[jj][1]);
        __half2 h1 = __floats2half2_rn(acc[jj][2], acc[jj][3]);
        __half2* dst = reinterpret_cast<__half2*>(
            g_KsuppH + (h * NSUPP + j0 + jb + jj) * NE + eb);
        dst[0] = h0;
        dst[1] = h1;
    }
    cudaTriggerProgrammaticLaunchCompletion();
}

// ---------------------------------------------------------------------------
// K1: user_fea_encode (data-independent of ksupp; runs concurrently via PDL).
// Ends with grid-sync so encode-complete implies ksupp-complete downstream.
// ---------------------------------------------------------------------------
__global__ void __launch_bounds__(128)
encode_kernel(const int* __restrict__ x,
              const int* __restrict__ src_his, const int* __restrict__ src_hl,
              const int* __restrict__ tgt_his, const int* __restrict__ tgt_hl,
              const float* __restrict__ src_user_emb,
              const float* __restrict__ tgt_user_emb,
              const float* __restrict__ src_item_emb,
              const float* __restrict__ W_att_w,
              const float* __restrict__ W_att_b,
              const float* __restrict__ W_agg_w) {
    int bx = blockIdx.x;
    int call = bx >> 10;
    int b = bx & (NB - 1);
    const int* his = call ? tgt_his : src_his;
    const int* hl  = call ? tgt_hl  : src_hl;
    const float* utab = call ? tgt_user_emb : src_user_emb;
    int tid = threadIdx.x, lane = tid & 31, warp = tid >> 5;

    __shared__ float Watt[NE * NE];
    __shared__ float hist[NLP * HSTRIDE];
    __shared__ float hsum[NLP];
    __shared__ float uv[NE], bbs[NE];
    __shared__ float att[NLP];
    __shared__ float outv[NE];
    __shared__ float part[2][NE];

    for (int i = tid; i < NE * NE / 4; i += 128)
        reinterpret_cast<float4*>(Watt)[i] = reinterpret_cast<const float4*>(W_att_w)[i];

    int hlen = hl[b];
    for (int i = tid; i < NLP * 16; i += 128) {
        int l = i >> 4, q = i & 15;
        float4 v = make_float4(0.f, 0.f, 0.f, 0.f);
        if (l < hlen) {
            int it = his[b * NL + l];
            v = *reinterpret_cast<const float4*>(src_item_emb + it * NE + q * 4);
        }
        *reinterpret_cast<float4*>(&hist[l * HSTRIDE + q * 4]) = v;
    }
    int uid = x[2 * b];
    if (tid < NE) {
        uv[tid]  = utab[uid * NE + tid];
        bbs[tid] = __ldg(W_att_b + tid);
    }
    __syncthreads();

    if (tid < NLP) {
        const float4* hp = reinterpret_cast<const float4*>(&hist[tid * HSTRIDE]);
        float s = 0.f;
#pragma unroll
        for (int k = 0; k < 16; k++) {
            float4 v = hp[k];
            s += (v.x + v.y) + (v.z + v.w);
        }
        hsum[tid] = s;
    }

    int eg = tid & 15, lg = tid >> 4;
    float4 bb = *reinterpret_cast<const float4*>(&bbs[eg * 4]);
    float4 acc[7];
#pragma unroll
    for (int i = 0; i < 7; i++) acc[i] = bb;

    const float4* W4 = reinterpret_cast<const float4*>(Watt);
#pragma unroll 2
    for (int ep4 = 0; ep4 < 16; ep4++) {
        float4 w0 = W4[(ep4 * 4 + 0) * 16 + eg];
        float4 w1 = W4[(ep4 * 4 + 1) * 16 + eg];
        float4 w2 = W4[(ep4 * 4 + 2) * 16 + eg];
        float4 w3 = W4[(ep4 * 4 + 3) * 16 + eg];
#pragma unroll
        for (int i = 0; i < 7; i++) {
            float4 hv = *reinterpret_cast<const float4*>(
                &hist[(lg + 8 * i) * HSTRIDE + ep4 * 4]);
            acc[i].x = fmaf(hv.x, w0.x, fmaf(hv.y, w1.x, fmaf(hv.z, w2.x, fmaf(hv.w, w3.x, acc[i].x))));
            acc[i].y = fmaf(hv.x, w0.y, fmaf(hv.y, w1.y, fmaf(hv.z, w2.y, fmaf(hv.w, w3.y, acc[i].y))));
            acc[i].z = fmaf(hv.x, w0.z, fmaf(hv.y, w1.z, fmaf(hv.z, w2.z, fmaf(hv.w, w3.z, acc[i].z))));
            acc[i].w = fmaf(hv.x, w0.w, fmaf(hv.y, w1.w, fmaf(hv.z, w2.w, fmaf(hv.w, w3.w, acc[i].w))));
        }
    }
    __syncthreads();

    float4 u4 = *reinterpret_cast<const float4*>(&uv[eg * 4]);
#pragma unroll
    for (int i = 0; i < 7; i++) {
        float p = fast_tanh(acc[i].x) * u4.x + fast_tanh(acc[i].y) * u4.y
                + fast_tanh(acc[i].z) * u4.z + fast_tanh(acc[i].w) * u4.w;
#pragma unroll
        for (int m = 1; m < 16; m <<= 1) p += __shfl_xor_sync(0xffffffffu, p, m);
        int l = lg + 8 * i;
        if (eg == 0 && l < NL) att[l] = (hsum[l] == 0.f) ? 0.f : p;
    }
    __syncthreads();

    if (warp == 0) {
        float mysum = 0.f;
        for (int l = lane; l < NL; l += 32) {
            float ex = __expf(att[l]);
            att[l] = ex;
            mysum += ex;
        }
#pragma unroll
        for (int o = 16; o; o >>= 1) mysum += __shfl_xor_sync(0xffffffffu, mysum, o);
        float inv = 1.f / (mysum + 1e-12f);
        for (int l = lane; l < NL; l += 32) att[l] *= inv;
    }
    __syncthreads();

    if (tid < NE) {
        float o = 0.f;
#pragma unroll
        for (int l = 0; l < NL; l++) o = fmaf(att[l], hist[l * HSTRIDE + tid], o);
        outv[tid] = o;
    }
    __syncthreads();

    {
        int o = tid & 63, half = tid >> 6;
        float f = 0.f;
        int e0 = half * 32;
#pragma unroll
        for (int ep = 0; ep < 32; ep++)
            f = fmaf(outv[e0 + ep], __ldg(W_agg_w + (e0 + ep) * NE + o), f);
        part[half][o] = f;
    }
    __syncthreads();
    if (tid < NE)
        g_fea[(call * NB + b) * NE + tid] = part[0][tid] + part[1][tid];

    // let attn launch early; then ensure ksupp is done before we complete,
    // so attn's single grid-sync transitively covers both producers.
    cudaTriggerProgrammaticLaunchCompletion();
    cudaGridDependencySynchronize();
}

// ---------------------------------------------------------------------------
// K2: attention with fused q/v projection. Prologue (inputs only) runs before
// the grid dependency sync; dependent reads (g_fea, g_KsuppH) after.
// dynamic smem: 256*72 halves = 36864 B.
// ---------------------------------------------------------------------------
__global__ void __launch_bounds__(256)
attn_kernel(const int* __restrict__ sample_idx,
            const float* __restrict__ Wq,
            const float* __restrict__ Wv) {
    extern __shared__ __half krows[];            // 256*72 halves
    __shared__ __half qh[NE];                    // q in half
    __shared__ __half2 swh[NS];                  // duplicated softmax weights
    __shared__ float reds[8];
    __shared__ float ctxp[8][NE];
    __shared__ float feas[NE];
    __shared__ float gpart[4][NE];
    __shared__ float ctxf[NE];
    __shared__ __align__(8) unsigned long long mbar;

    int bx = blockIdx.x;
    int call = bx >> 12;
    int h = (bx >> 10) & 3;
    int b = bx & (NB - 1);
    int tid = threadIdx.x, lane = tid & 31, warp = tid >> 5;
    int row = (call * NH + h) * NB + b;
    int e = tid & 63, p = tid >> 6;

    // prologue on inputs only (overlaps encode's tail via PDL)
    unsigned mb = smem_u32(&mbar);
    if (tid == 0) mbar_init(mb, 1);
    int j = sample_idx[(row << 8) + tid];
    __syncthreads();
    if (tid == 0) mbar_expect_tx(mb, NS * NE * 2);   // 32768 bytes

    cudaGridDependencySynchronize();                 // wait for encode (=> ksupp)

    bulk_copy128(krows + tid * KH, g_KsuppH + (h * NSUPP + j) * NE, mb);

    // ---- fused q projection (overlaps the TMA gather) ----
    if (tid < NE) feas[tid] = g_fea[(call * NB + b) * NE + tid];
    __syncthreads();
    {
        const float* wq = Wq + h * NE * NE + e;
        float a = 0.f;
        int e0 = p * 16;
#pragma unroll
        for (int ep = 0; ep < 16; ep++)
            a = fmaf(feas[e0 + ep], __ldg(wq + (e0 + ep) * NE), a);
        gpart[p][e] = a;
    }
    __syncthreads();
    if (tid < 32) {
        float q0 = gpart[0][2 * tid] + gpart[1][2 * tid]
                 + gpart[2][2 * tid] + gpart[3][2 * tid];
        float q1 = gpart[0][2 * tid + 1] + gpart[1][2 * tid + 1]
                 + gpart[2][2 * tid + 1] + gpart[3][2 * tid + 1];
        *reinterpret_cast<__half2*>(&qh[2 * tid]) = __floats2half2_rn(q0, q1);
    }
    __syncthreads();
    mbar_wait(mb, 0);

    // scores: thread tid owns smem row tid; packed half2 dot, fp32 outer sum
    float myscore;
    {
        const uint4* r4 = reinterpret_cast<const uint4*>(krows + tid * KH);
        const uint4* q4 = reinterpret_cast<const uint4*>(qh);
        float a = 0.f;
#pragma unroll
        for (int c = 0; c < 8; c++) {
            uint4 kk = r4[c];
            uint4 qq = q4[c];
            __half2 pp = __hmul2(u2h2(kk.x), u2h2(qq.x));
            pp = __hfma2(u2h2(kk.y), u2h2(qq.y), pp);
            pp = __hfma2(u2h2(kk.z), u2h2(qq.z), pp);
            pp = __hfma2(u2h2(kk.w), u2h2(qq.w), pp);
            float2 f = __half22float2(pp);
            a += f.x + f.y;
        }
        myscore = a;
    }

    // softmax without max-subtraction (scores are tiny)
    float ex = __expf(myscore);
    float ls = ex;
#pragma unroll
    for (int o = 16; o; o >>= 1) ls += __shfl_xor_sync(0xffffffffu, ls, o);
    if (lane == 0) reds[warp] = ls;
    __syncthreads();
    float tot = reds[0];
#pragma unroll
    for (int w = 1; w < 8; w++) tot += reds[w];
    float myw = ex * fast_rcp(tot);
    swh[tid] = __float2half2_rn(myw);
    __syncthreads();

    // ctx: warp w owns rows [32w,32w+32); lane owns e-pair (2lane, 2lane+1).
    {
        const __half2* kr2 = reinterpret_cast<const __half2*>(krows)
                           + (warp * 32) * (KH / 2) + lane;
        const __half2* wp = swh + warp * 32;
        __half2 acc0 = __float2half2_rn(0.f), acc1 = acc0, acc2 = acc0, acc3 = acc0;
#pragma unroll
        for (int i = 0; i < 32; i += 4) {
            acc0 = __hfma2(wp[i + 0], kr2[(i + 0) * (KH / 2)], acc0);
            acc1 = __hfma2(wp[i + 1], kr2[(i + 1) * (KH / 2)], acc1);
            acc2 = __hfma2(wp[i + 2], kr2[(i + 2) * (KH / 2)], acc2);
            acc3 = __hfma2(wp[i + 3], kr2[(i + 3) * (KH / 2)], acc3);
        }
        float2 f0 = __half22float2(acc0);
        float2 f1 = __half22float2(acc1);
        float2 f2 = __half22float2(acc2);
        float2 f3 = __half22float2(acc3);
        ctxp[warp][2 * lane]     = (f0.x + f1.x) + (f2.x + f3.x);
        ctxp[warp][2 * lane + 1] = (f0.y + f1.y) + (f2.y + f3.y);
    }
    __syncthreads();
    if (tid < NE) {
        float cs = 0.f;
#pragma unroll
        for (int w = 0; w < 8; w++) cs += ctxp[w][tid];
        ctxf[tid] = cs;
    }
    __syncthreads();
    cudaTriggerProgrammaticLaunchCompletion();   // let final start staging

    // ---- fused v projection: g = ctx @ Wv[h] ----
    {
        const float* wv = Wv + h * NE * NE + e;
        float a = 0.f;
        int e0 = p * 16;
#pragma unroll
        for (int ep = 0; ep < 16; ep++)
            a = fmaf(ctxf[e0 + ep], __ldg(wv + (e0 + ep) * NE), a);
        gpart[p][e] = a;
    }
    __syncthreads();
    if (tid < NE)
        g_g[row * NE + tid] = (gpart[0][tid] + gpart[1][tid])
                            + (gpart[2][tid] + gpart[3][tid]);
}

// ---------------------------------------------------------------------------
// K3: 4 b per block; stages W_out (input) BEFORE the grid sync, then reads
// g_g after. l1_w/l2_w restaged later.
// out layout: [output(1024) | x3(1024) | out_emb_s(65536) | x2(65536)]
// ---------------------------------------------------------------------------
__global__ void __launch_bounds__(256)
final_kernel(const int* __restrict__ x,
             const float* __restrict__ tgt_item_emb,
             const float* __restrict__ W_out,
             const float* __restrict__ l1_w, const float* __restrict__ l1_b,
             const float* __restrict__ l2_w, const float* __restrict__ l2_b,
             const float* __restrict__ l3_w, const float* __restrict__ l3_b,
             float* __restrict__ out) {
    extern __shared__ float Wo[];
    __shared__ float gs0[4][NH * NE], gs1[4][NH * NE];
    __shared__ float sue[4][NE], she[4][NE];
    __shared__ float xvs[4][2 * NE], x1ss[4][NE];

    int tid = threadIdx.x;
    int b0 = blockIdx.x * 4;

    // stage W_out (input) while attn drains
    for (int i = tid; i < 4096; i += 256)
        reinterpret_cast<float4*>(Wo)[i] = reinterpret_cast<const float4*>(W_out)[i];

    cudaGridDependencySynchronize();             // wait for attn's g_g

    for (int i = tid; i < 4 * 256; i += 256) {
        int bq = i >> 8, k = i & 255;
        int h = k >> 6, e = k & 63;
        gs0[bq][k] = g_g[(h * NB + b0 + bq) * NE + e];
        gs1[bq][k] = g_g[((NH + h) * NB + b0 + bq) * NE + e];
    }
    __syncthreads();

    {
        int e = tid & 63, bq = tid >> 6;
        float ue = 0.f, he = 0.f;
#pragma unroll 8
        for (int i = 0; i < 256; i++) {
            float w = Wo[i * NE + e];
            ue = fmaf(gs0[bq][i], w, ue);
            he = fmaf(gs1[bq][i], w, he);
        }
        sue[bq][e] = ue;
        she[bq][e] = he;
    }
    __syncthreads();

    for (int i = tid; i < 2048; i += 256)
        reinterpret_cast<float4*>(Wo)[i] = reinterpret_cast<const float4*>(l1_w)[i];
    for (int i = tid; i < 1024; i += 256)
        reinterpret_cast<float4*>(Wo)[2048 + i] = reinterpret_cast<const float4*>(l2_w)[i];

    int lane = tid & 31, warp = tid >> 5;
    if (warp < 4) {
        int b = b0 + warp;
        int item = x[2 * b + 1];
        float iv0 = tgt_item_emb[item * NE + lane];
        float iv1 = tgt_item_emb[item * NE + 32 + lane];
        float ue0 = sue[warp][lane], ue1 = sue[warp][32 + lane];
        float he0 = she[warp][lane], he1 = she[warp][32 + lane];
        float p0 = ue0 * iv0, p1 = ue1 * iv1;
        out[2 * NB + b * NE + lane] = p0;
        out[2 * NB + b * NE + 32 + lane] = p1;
        float r = p0 + p1;
#pragma unroll
        for (int o = 16; o; o >>= 1) r += __shfl_xor_sync(0xffffffffu, r, o);
        if (lane == 0) out[b] = r;
        xvs[warp][lane] = he0;
        xvs[warp][32 + lane] = he1;
        xvs[warp][64 + lane] = iv0;
        xvs[warp][96 + lane] = iv1;
    }
    __syncthreads();

    if (warp < 4) {
        int b = b0 + warp;
        float a0 = __ldg(l1_b + lane), a1 = __ldg(l1_b + 32 + lane);
#pragma unroll 4
        for (int i = 0; i < 128; i++) {
            float xv = xvs[warp][i];
            a0 = fmaf(xv, Wo[i * NE + lane], a0);
            a1 = fmaf(xv, Wo[i * NE + 32 + lane], a1);
        }
        x1ss[warp][lane] = fast_tanh(a0);
        x1ss[warp][32 + lane] = fast_tanh(a1);
        __syncwarp();
        float c0 = __ldg(l2_b + lane), c1 = __ldg(l2_b + 32 + lane);
#pragma unroll 4
        for (int i = 0; i < 64; i++) {
            float xv = x1ss[warp][i];
            c0 = fmaf(xv, Wo[8192 + i * NE + lane], c0);
            c1 = fmaf(xv, Wo[8192 + i * NE + 32 + lane], c1);
        }
        float x20 = fast_tanh(c0), x21 = fast_tanh(c1);
        out[2 * NB + NB * NE + b * NE + lane] = x20;
        out[2 * NB + NB * NE + b * NE + 32 + lane] = x21;
        float r3 = x20 * __ldg(l3_w + lane) + x21 * __ldg(l3_w + 32 + lane);
#pragma unroll
        for (int o = 16; o; o >>= 1) r3 += __shfl_xor_sync(0xffffffffu, r3, o);
        if (lane == 0) out[NB + b] = r3 + __ldg(l3_b);
    }
}

// ---------------------------------------------------------------------------
extern "C" void kernel_launch(void* const* d_in, const int* in_sizes, int n_in,
                              void* d_out, int out_size) {
    const int* x            = (const int*)d_in[0];
    const int* src_his      = (const int*)d_in[1];
    const int* src_hl       = (const int*)d_in[2];
    const int* tgt_his      = (const int*)d_in[3];
    const int* tgt_hl       = (const int*)d_in[4];
    const int* sample_idx   = (const int*)d_in[5];
    const int* supp_users   = (const int*)d_in[6];
    const float* src_user_emb = (const float*)d_in[7];
    const float* src_item_emb = (const float*)d_in[8];
    const float* tgt_user_emb = (const float*)d_in[9];
    const float* tgt_item_emb = (const float*)d_in[10];
    const float* W_att_w    = (const float*)d_in[11];
    const float* W_att_b    = (const float*)d_in[12];
    const float* W_agg_w    = (const float*)d_in[13];
    const float* Wq         = (const float*)d_in[14];
    const float* Wk         = (const float*)d_in[15];
    const float* Wv         = (const float*)d_in[16];
    const float* W_out      = (const float*)d_in[17];
    const float* l1_w       = (const float*)d_in[18];
    const float* l1_b       = (const float*)d_in[19];
    const float* l2_w       = (const float*)d_in[20];
    const float* l2_b       = (const float*)d_in[21];
    const float* l3_w       = (const float*)d_in[22];
    const float* l3_b       = (const float*)d_in[23];
    float* out = (float*)d_out;

    size_t big = 65536;
    size_t asmem = (size_t)NS * KH * sizeof(__half);   // 36864
    cudaFuncSetAttribute(ksupp_kernel, cudaFuncAttributeMaxDynamicSharedMemorySize, (int)big);
    cudaFuncSetAttribute(attn_kernel, cudaFuncAttributeMaxDynamicSharedMemorySize, (int)asmem);
    cudaFuncSetAttribute(final_kernel, cudaFuncAttributeMaxDynamicSharedMemorySize, (int)big);

    cudaLaunchAttribute pdl[1];
    pdl[0].id = cudaLaunchAttributeProgrammaticStreamSerialization;
    pdl[0].val.programmaticStreamSerializationAllowed = 1;

    // K0: normal launch
    ksupp_kernel<<<NSUPP / 16, 256, big>>>(supp_users, tgt_user_emb, Wk);

    // K1: PDL (independent of ksupp; overlaps its tail)
    {
        cudaLaunchConfig_t cfg = {};
        cfg.gridDim = dim3(2 * NB);
        cfg.blockDim = dim3(128);
        cfg.dynamicSmemBytes = 0;
        cfg.stream = 0;
        cfg.attrs = pdl;
        cfg.numAttrs = 1;
        cudaLaunchKernelEx(&cfg, encode_kernel, x, src_his, src_hl, tgt_his, tgt_hl,
                           src_user_emb, tgt_user_emb, src_item_emb,
                           W_att_w, W_att_b, W_agg_w);
    }

    // K2: PDL (prologue overlaps encode tail; grid-sync before dependent reads)
    {
        cudaLaunchConfig_t cfg = {};
        cfg.gridDim = dim3(2 * NH * NB);
        cfg.blockDim = dim3(256);
        cfg.dynamicSmemBytes = asmem;
        cfg.stream = 0;
        cfg.attrs = pdl;
        cfg.numAttrs = 1;
        cudaLaunchKernelEx(&cfg, attn_kernel, sample_idx, Wq, Wv);
    }

    // K3: PDL (W_out staging overlaps attn tail)
    {
        cudaLaunchConfig_t cfg = {};
        cfg.gridDim = dim3(NB / 4);
        cfg.blockDim = dim3(256);
        cfg.dynamicSmemBytes = big;
        cfg.stream = 0;
        cfg.attrs = pdl;
        cfg.numAttrs = 1;
        cudaLaunchKernelEx(&cfg, final_kernel, x, tgt_item_emb, W_out,
                           l1_w, l1_b, l2_w, l2_b, l3_w, l3_b, out);
    }
}